// round 10
// baseline (speedup 1.0000x reference)
#include <cuda_runtime.h>
#include <cuda_bf16.h>
#include <cstdint>

// Problem constants
#define BB 32
#define CC 256
#define HW 1024
#define NROWS 32768
#define KCODES 2048
#define DEPTH 4

// GEMM: CTA 128(M) x 128(N), 128 threads = 4 warps as 2(M) x 2(N), warp 64x64
#define CTA_M 128
#define CTA_N 128
#define STAGES 4
#define NTILES (KCODES / CTA_N)   // 16 partials per row

// ---------------- scratch (device globals; no allocations) ----------------
__device__ float g_res[(size_t)NROWS * CC];        // residual [r][c] fp32
__device__ __nv_bfloat16 g_abf[(size_t)NROWS * CC];// residual bf16 (per depth)
__device__ __nv_bfloat16 g_cbbf[(size_t)KCODES * CC];
__device__ float g_enorm[KCODES];
__device__ float g_tmin[(size_t)NROWS * (KCODES / 8)];  // per 8-code group min
__device__ ulonglong2 g_part[(size_t)NROWS * NTILES];   // per-tile (min1key, min2key)
__device__ unsigned long long g_best[NROWS];
__device__ int g_counts[KCODES];

static __device__ __forceinline__ unsigned smem_u32(const void* p) {
    return (unsigned)__cvta_generic_to_shared(p);
}
static __device__ __forceinline__ void ldsm4(uint32_t* r, unsigned addr) {
    asm volatile("ldmatrix.sync.aligned.m8n8.x4.shared.b16 {%0,%1,%2,%3}, [%4];"
                 : "=r"(r[0]), "=r"(r[1]), "=r"(r[2]), "=r"(r[3]) : "r"(addr));
}
static __device__ __forceinline__ void mma16816(float* c, const uint32_t* a,
                                                uint32_t b0, uint32_t b1) {
    asm volatile(
        "mma.sync.aligned.m16n8k16.row.col.f32.bf16.bf16.f32 "
        "{%0,%1,%2,%3},{%4,%5,%6,%7},{%8,%9},{%0,%1,%2,%3};"
        : "+f"(c[0]), "+f"(c[1]), "+f"(c[2]), "+f"(c[3])
        : "r"(a[0]), "r"(a[1]), "r"(a[2]), "r"(a[3]), "r"(b0), "r"(b1));
}
static __device__ __forceinline__ void cpasync16(unsigned saddr, const void* g) {
    asm volatile("cp.async.cg.shared.global [%0], [%1], 16;"
                 :: "r"(saddr), "l"(g));
}
static __device__ __forceinline__ unsigned pack_bf2(float x, float y) {
    unsigned short a = __bfloat16_as_ushort(__float2bfloat16_rn(x));
    unsigned short b = __bfloat16_as_ushort(__float2bfloat16_rn(y));
    return (unsigned)a | ((unsigned)b << 16);
}
// merge two (min1,min2) key pairs
static __device__ __forceinline__ void merge2(unsigned long long& k1,
                                              unsigned long long& k2,
                                              unsigned long long o1,
                                              unsigned long long o2) {
    unsigned long long n1 = min(k1, o1);
    unsigned long long n2 = min(max(k1, o1), min(k2, o2));
    k1 = n1; k2 = n2;
}

// ---------------- setup kernels ----------------

// z [B][C][HW] -> g_res[r][c] fp32 + g_abf bf16 (depth-0 conversion fused)
__global__ void k_init_transpose(const float* __restrict__ z) {
    __shared__ float T[32][33];
    int b = blockIdx.z, hw0 = blockIdx.y * 32, c0 = blockIdx.x * 32;
    int tx = threadIdx.x & 31, ty0 = threadIdx.x >> 5;
#pragma unroll
    for (int p = 0; p < 4; p++) {
        int cl = ty0 + p * 8;
        T[cl][tx] = z[((size_t)(b * CC + c0 + cl)) * HW + hw0 + tx];
    }
    __syncthreads();
#pragma unroll
    for (int p = 0; p < 4; p++) {
        int hwl = ty0 + p * 8;
        size_t a = (size_t)(b * HW + hw0 + hwl) * CC + c0 + tx;
        float v = T[tx][hwl];
        g_res[a] = v;
        g_abf[a] = __float2bfloat16_rn(v);
    }
}

// codebook norms + bf16 copy + zero counts (once)
__global__ void k_enorm_bf16(const float* __restrict__ cb) {
    int row = blockIdx.x * 8 + (threadIdx.x >> 5);
    int lane = threadIdx.x & 31;
    const float4* p = (const float4*)&cb[(size_t)row * CC + lane * 8];
    float4 v0 = p[0], v1 = p[1];
    uint4 u;
    u.x = pack_bf2(v0.x, v0.y); u.y = pack_bf2(v0.z, v0.w);
    u.z = pack_bf2(v1.x, v1.y); u.w = pack_bf2(v1.z, v1.w);
    *(uint4*)&g_cbbf[(size_t)row * CC + lane * 8] = u;
    float s = v0.x*v0.x + v0.y*v0.y + v0.z*v0.z + v0.w*v0.w
            + v1.x*v1.x + v1.y*v1.y + v1.z*v1.z + v1.w*v1.w;
#pragma unroll
    for (int m = 16; m >= 1; m >>= 1) s += __shfl_xor_sync(0xffffffffu, s, m);
    if (lane == 0) {
        g_enorm[row] = s;
        g_counts[row] = 0;
    }
}

// ---------------- phase 1: bf16 MMA low-precision distances ----------------
// 128 threads, CTA 128x128, warp tile 64x64, cp.async 4-stage pipeline.
// Writes g_tmin[row][group] (8-code group mins) and g_part[row][tile] =
// (min1key, min2key) over this tile's 128 codes, key = (bits(d+4)<<32)|code.
__global__ void __launch_bounds__(128) k_lowdist() {
    __shared__ __nv_bfloat16 As[STAGES][CTA_M][40];
    __shared__ __nv_bfloat16 Bs[STAGES][CTA_N][40];
    __shared__ float enS[CTA_N];
    __shared__ ulonglong2 pm[CTA_M][2];

    int tid = threadIdx.x;
    int wid = tid >> 5, l = tid & 31;
    int wm = (wid & 1) * 64, wn = (wid >> 1) * 64;
    int row0 = blockIdx.y * CTA_M, n0 = blockIdx.x * CTA_N;

    enS[tid] = g_enorm[n0 + tid];

    float acc[4][8][4];
#pragma unroll
    for (int i = 0; i < 4; i++)
#pragma unroll
        for (int j = 0; j < 8; j++)
#pragma unroll
            for (int c = 0; c < 4; c++) acc[i][j][c] = 0.0f;

    auto issue = [&](int ch, int st) {
        int kc = ch * 32;
#pragma unroll
        for (int i = 0; i < 4; i++) {
            int idx = tid + i * 128;
            int r = idx >> 2, c16 = idx & 3;
            cpasync16(smem_u32(&As[st][r][c16 * 8]),
                      &g_abf[(size_t)(row0 + r) * CC + kc + c16 * 8]);
        }
#pragma unroll
        for (int i = 0; i < 4; i++) {
            int idx = tid + i * 128;
            int r = idx >> 2, c16 = idx & 3;
            cpasync16(smem_u32(&Bs[st][r][c16 * 8]),
                      &g_cbbf[(size_t)(n0 + r) * CC + kc + c16 * 8]);
        }
        asm volatile("cp.async.commit_group;" ::: "memory");
    };

    issue(0, 0);
    issue(1, 1);
    issue(2, 2);

#pragma unroll
    for (int ch = 0; ch < 8; ch++) {
        if (ch >= 7) {
            asm volatile("cp.async.wait_group 0;" ::: "memory");
        } else if (ch == 6) {
            asm volatile("cp.async.wait_group 1;" ::: "memory");
        } else {
            asm volatile("cp.async.wait_group 2;" ::: "memory");
        }
        __syncthreads();
        if (ch + 3 < 8) issue(ch + 3, (ch + 3) % STAGES);

        int st = ch % STAGES;
#pragma unroll
        for (int kh = 0; kh < 2; kh++) {
            uint32_t a[4][4], bfr[4][4];
#pragma unroll
            for (int i = 0; i < 4; i++) {
                int m = wm + i * 16 + (l & 15);
                unsigned ad = smem_u32(&As[st][m][0]) + ((l >> 4) + kh * 2) * 16;
                ldsm4(a[i], ad);
            }
#pragma unroll
            for (int jj = 0; jj < 4; jj++) {
                int n = wn + jj * 16 + (l & 15);
                unsigned ad = smem_u32(&Bs[st][n][0]) + ((l >> 4) + kh * 2) * 16;
                ldsm4(bfr[jj], ad);
            }
#pragma unroll
            for (int i = 0; i < 4; i++)
#pragma unroll
                for (int j = 0; j < 8; j++)
                    mma16816(acc[i][j], a[i], bfr[j >> 1][j & 1], bfr[j >> 1][(j & 1) + 2]);
        }
    }

    // epilogue: group-of-8 mins (g_tmin) + per-row two-min keys (g_part)
#pragma unroll
    for (int i = 0; i < 4; i++) {
#pragma unroll
        for (int h = 0; h < 2; h++) {
            float gv[8];
            unsigned long long k1 = ~0ull, k2 = ~0ull;
#pragma unroll
            for (int j = 0; j < 8; j++) {
                int nl = wn + j * 8 + (l & 3) * 2;
                float d0 = enS[nl]     - 2.0f * acc[i][j][h * 2 + 0];
                float d1 = enS[nl + 1] - 2.0f * acc[i][j][h * 2 + 1];
                gv[j] = fminf(d0, d1);
                unsigned long long key0 =
                    ((unsigned long long)__float_as_uint(4.0f + d0) << 32)
                    | (unsigned)(n0 + nl);
                unsigned long long key1 =
                    ((unsigned long long)__float_as_uint(4.0f + d1) << 32)
                    | (unsigned)(n0 + nl + 1);
                if (key0 < k1) { k2 = k1; k1 = key0; } else if (key0 < k2) k2 = key0;
                if (key1 < k1) { k2 = k1; k1 = key1; } else if (key1 < k2) k2 = key1;
            }
#pragma unroll
            for (int j = 0; j < 8; j++) {
                gv[j] = fminf(gv[j], __shfl_xor_sync(0xffffffffu, gv[j], 1));
                gv[j] = fminf(gv[j], __shfl_xor_sync(0xffffffffu, gv[j], 2));
            }
#pragma unroll
            for (int m = 1; m <= 2; m <<= 1) {
                unsigned long long o1 = __shfl_xor_sync(0xffffffffu, k1, m);
                unsigned long long o2 = __shfl_xor_sync(0xffffffffu, k2, m);
                merge2(k1, k2, o1, o2);
            }
            if ((l & 3) == 0) {
                int rloc = wm + i * 16 + h * 8 + (l >> 2);
                float4* dst = (float4*)&g_tmin[(size_t)(row0 + rloc) * (KCODES / 8)
                                               + ((n0 + wn) >> 3)];
                dst[0] = make_float4(gv[0], gv[1], gv[2], gv[3]);
                dst[1] = make_float4(gv[4], gv[5], gv[6], gv[7]);
                pm[rloc][wn >> 6] = make_ulonglong2(k1, k2);
            }
        }
    }
    __syncthreads();
    if (tid < CTA_M) {
        ulonglong2 a = pm[tid][0], b = pm[tid][1];
        unsigned long long m1 = min(a.x, b.x);
        unsigned long long m2 = min(max(a.x, b.x), min(a.y, b.y));
        g_part[(size_t)(row0 + tid) * NTILES + blockIdx.x] = make_ulonglong2(m1, m2);
    }
}

// ---------------- phase 2: gap-skip + exact fp32 refine ----------------
// Decided rows (prune gap > GAP): take the prune argmin directly.
// Undecided rows: exact strict-sequential fp32 refine (proven bit-compatible).
#define CLIST 256
__global__ void __launch_bounds__(256) k_refine(const float* __restrict__ cb) {
    __shared__ float zsh[8][256];
    __shared__ int clist[8][CLIST];
    __shared__ int ccnt[8];
    const float MARGIN = 5e-4f;
    const float GAP = 6e-4f;
    int wid = threadIdx.x >> 5, l = threadIdx.x & 31;
    int r = blockIdx.x * 8 + wid;

    // ---- gap decision from g_part (256B per row) ----
    unsigned long long k1 = ~0ull, k2 = ~0ull;
    if (l < NTILES) {
        ulonglong2 p = g_part[(size_t)r * NTILES + l];
        k1 = p.x; k2 = p.y;
    }
#pragma unroll
    for (int m = 1; m <= 8; m <<= 1) {
        unsigned long long o1 = __shfl_xor_sync(0xffffffffu, k1, m);
        unsigned long long o2 = __shfl_xor_sync(0xffffffffu, k2, m);
        merge2(k1, k2, o1, o2);
    }
    k1 = __shfl_sync(0xffffffffu, k1, 0);
    k2 = __shfl_sync(0xffffffffu, k2, 0);
    float m1v = __uint_as_float((unsigned)(k1 >> 32));
    float m2v = __uint_as_float((unsigned)(k2 >> 32));
    if (m2v - m1v > GAP) {
        if (l == 0) g_best[r] = k1;   // gather uses low 32 bits (code index)
        return;
    }

    // ---- undecided: exact refine ----
    const float4* zr = (const float4*)&g_res[(size_t)r * CC];
    float4* zs4 = (float4*)zsh[wid];
    zs4[l] = zr[l];
    zs4[l + 32] = zr[l + 32];
    if (l == 0) ccnt[wid] = 0;
    __syncwarp();

    float zn;
    {
        const float4* p = (const float4*)&zsh[wid][l * 8];
        float4 v0 = p[0], v1 = p[1];
        float s = v0.x*v0.x + v0.y*v0.y + v0.z*v0.z + v0.w*v0.w
                + v1.x*v1.x + v1.y*v1.y + v1.z*v1.z + v1.w*v1.w;
#pragma unroll
        for (int m = 16; m >= 1; m >>= 1) s += __shfl_xor_sync(0xffffffffu, s, m);
        zn = s;
    }

    float v[8];
    const float* tmr = &g_tmin[(size_t)r * (KCODES / 8)];
    float gmin = 3.0e38f;
#pragma unroll
    for (int s = 0; s < 8; s++) {
        v[s] = tmr[s * 32 + l];
        gmin = fminf(gmin, v[s]);
    }
#pragma unroll
    for (int m = 16; m >= 1; m >>= 1)
        gmin = fminf(gmin, __shfl_xor_sync(0xffffffffu, gmin, m));
    float thresh = gmin + MARGIN;

#pragma unroll
    for (int s = 0; s < 8; s++) {
        if (v[s] <= thresh) {
            int g = s * 32 + l;
            int pos = atomicAdd(&ccnt[wid], 8);
            if (pos <= CLIST - 8) {
#pragma unroll
                for (int k = 0; k < 8; k++) clist[wid][pos + k] = g * 8 + k;
            }
        }
    }
    __syncwarp();
    int cnt = ccnt[wid];

    const float4* zc = (const float4*)zsh[wid];
    unsigned long long best = 0xFFFFFFFFFFFFFFFFull;

    if (cnt <= CLIST - 8) {
        for (int base = 0; base < cnt; base += 32) {
            int ci = base + l;
            if (ci < cnt) {
                int code = clist[wid][ci];
                const float4* e4 = (const float4*)&cb[(size_t)code * CC];
                float dot = 0.0f;
#pragma unroll 8
                for (int i = 0; i < 64; i++) {
                    float4 zv = zc[i], ev = e4[i];
                    dot = fmaf(zv.x, ev.x, dot);
                    dot = fmaf(zv.y, ev.y, dot);
                    dot = fmaf(zv.z, ev.z, dot);
                    dot = fmaf(zv.w, ev.w, dot);
                }
                float dist = (zn + g_enorm[code]) - 2.0f * dot;
                unsigned long long key =
                    ((unsigned long long)__float_as_uint(dist) << 32) | (unsigned)code;
                best = min(best, key);
            }
        }
    } else {
        for (int base = 0; base < KCODES; base += 32) {
            int code = base + l;
            const float4* e4 = (const float4*)&cb[(size_t)code * CC];
            float dot = 0.0f;
#pragma unroll 8
            for (int i = 0; i < 64; i++) {
                float4 zv = zc[i], ev = e4[i];
                dot = fmaf(zv.x, ev.x, dot);
                dot = fmaf(zv.y, ev.y, dot);
                dot = fmaf(zv.z, ev.z, dot);
                dot = fmaf(zv.w, ev.w, dot);
            }
            float dist = (zn + g_enorm[code]) - 2.0f * dot;
            unsigned long long key =
                ((unsigned long long)__float_as_uint(dist) << 32) | (unsigned)code;
            best = min(best, key);
        }
    }

#pragma unroll
    for (int m = 16; m >= 1; m >>= 1) {
        unsigned long long o = __shfl_xor_sync(0xffffffffu, best, m);
        best = min(best, o);
    }
    if (l == 0) g_best[r] = best;
}

// ---------------- gather/update/outputs ----------------
__global__ void k_gather_update(const float* __restrict__ cb,
                                float* __restrict__ out_cum,
                                float* __restrict__ out_st,
                                float* __restrict__ out_idx,
                                int d) {
    __shared__ int idx_s[32];
    __shared__ float Tq[32][33];
    __shared__ float Tr[32][33];
    int b = blockIdx.z, hw0 = blockIdx.y * 32, c0 = blockIdx.x * 32;
    int tx = threadIdx.x & 31, ty0 = threadIdx.x >> 5;

    if (threadIdx.x < 32) {
        int r = b * HW + hw0 + threadIdx.x;
        unsigned long long k = g_best[r];
        int idx = (int)(k & 0xFFFFFFFFull);
        idx_s[threadIdx.x] = idx;
        if (c0 == 0) {
            if (out_idx) out_idx[d * NROWS + r] = (float)idx;
            atomicAdd(&g_counts[idx], 1);
        }
    }
    __syncthreads();
#pragma unroll
    for (int p = 0; p < 4; p++) {
        int hwl = ty0 + p * 8;
        int r = b * HW + hw0 + hwl;
        int c = c0 + tx;
        float q = cb[(size_t)idx_s[hwl] * CC + c];
        size_t a = (size_t)r * CC + c;
        float res = g_res[a] - q;
        g_res[a] = res;
        if (d < DEPTH - 1) g_abf[a] = __float2bfloat16_rn(res);
        Tq[tx][hwl] = q;
        Tr[tx][hwl] = res;
    }
    __syncthreads();
#pragma unroll
    for (int p = 0; p < 4; p++) {
        int cl = ty0 + p * 8;
        size_t o = ((size_t)(d * BB + b) * CC + c0 + cl) * HW + hw0 + tx;
        float cum = Tq[cl][tx];
        if (d > 0) {
            size_t oprev = ((size_t)((d - 1) * BB + b) * CC + c0 + cl) * HW + hw0 + tx;
            cum = out_cum[oprev] + cum;
        }
        out_cum[o] = cum;
        if (d == DEPTH - 1 && out_st) {
            out_st[((size_t)b * CC + c0 + cl) * HW + hw0 + tx] = Tr[cl][tx];
        }
    }
}

__global__ void k_perplexity(float* __restrict__ out_perp) {
    __shared__ float red[256];
    float s = 0.0f;
    const float inv = 1.0f / (float)(DEPTH * NROWS);
    for (int k = threadIdx.x; k < KCODES; k += 256) {
        float p = (float)g_counts[k] * inv;
        if (p > 0.0f) s += p * logf(p);
    }
    red[threadIdx.x] = s;
    __syncthreads();
    for (int m = 128; m >= 1; m >>= 1) {
        if (threadIdx.x < m) red[threadIdx.x] += red[threadIdx.x + m];
        __syncthreads();
    }
    if (threadIdx.x == 0) *out_perp = expf(-red[0]);
}

// ---------------- launch ----------------
extern "C" void kernel_launch(void* const* d_in, const int* in_sizes, int n_in,
                              void* d_out, int out_size) {
    const float* z = (const float*)d_in[0];
    const float* cb = (const float*)d_in[1];
    float* out = (float*)d_out;

    const long long SZ_CUM = (long long)DEPTH * BB * CC * HW;
    const long long SZ_ST = (long long)BB * CC * HW;
    const long long SZ_IDX = (long long)DEPTH * NROWS;

    float* out_cum = out;
    float* out_st = (out_size >= SZ_CUM + SZ_ST) ? out + SZ_CUM : nullptr;
    float* out_idx = (out_size >= SZ_CUM + SZ_ST + SZ_IDX) ? out + SZ_CUM + SZ_ST : nullptr;
    float* out_perp = (out_size >= SZ_CUM + SZ_ST + SZ_IDX + 1)
                          ? out + SZ_CUM + SZ_ST + SZ_IDX : nullptr;

    dim3 tgrid(CC / 32, HW / 32, BB);
    k_init_transpose<<<tgrid, 256>>>(z);        // launch 1
    k_enorm_bf16<<<KCODES / 8, 256>>>(cb);      // launch 2 (also zeroes counts)

    for (int d = 0; d < DEPTH; d++) {
        k_lowdist<<<dim3(KCODES / CTA_N, NROWS / CTA_M), 128>>>(); // launch 3 at d=0
        k_refine<<<NROWS / 8, 256>>>(cb);                          // launch 4 at d=0 -> profiled
        k_gather_update<<<tgrid, 256>>>(cb, out_cum, out_st, out_idx, d);
    }
    if (out_perp) k_perplexity<<<1, 256>>>(out_perp);
}

// round 11
// speedup vs baseline: 1.1340x; 1.1340x over previous
#include <cuda_runtime.h>
#include <cuda_bf16.h>
#include <cstdint>

// Problem constants
#define BB 32
#define CC 256
#define HW 1024
#define NROWS 32768
#define KCODES 2048
#define DEPTH 4

// GEMM: CTA 128(M) x 128(N), 128 threads = 4 warps as 2(M) x 2(N), warp 64x64
#define CTA_M 128
#define CTA_N 128
#define STAGES 4
#define NTILES (KCODES / CTA_N)   // 16 partials per row

// ---------------- scratch (device globals; no allocations) ----------------
__device__ float g_res[(size_t)NROWS * CC];        // residual [r][c] fp32
__device__ __nv_bfloat16 g_abf[(size_t)NROWS * CC];// residual bf16 (per depth)
__device__ __nv_bfloat16 g_cbbf[(size_t)KCODES * CC];
__device__ float g_enorm[KCODES];
__device__ float g_tmin[(size_t)NROWS * (KCODES / 8)];  // per 8-code group min
__device__ ulonglong2 g_part[(size_t)NROWS * NTILES];   // per-tile (min1key, min2key)
__device__ unsigned long long g_best[NROWS];
__device__ int g_counts[KCODES];

static __device__ __forceinline__ unsigned smem_u32(const void* p) {
    return (unsigned)__cvta_generic_to_shared(p);
}
static __device__ __forceinline__ void ldsm4(uint32_t* r, unsigned addr) {
    asm volatile("ldmatrix.sync.aligned.m8n8.x4.shared.b16 {%0,%1,%2,%3}, [%4];"
                 : "=r"(r[0]), "=r"(r[1]), "=r"(r[2]), "=r"(r[3]) : "r"(addr));
}
static __device__ __forceinline__ void mma16816(float* c, const uint32_t* a,
                                                uint32_t b0, uint32_t b1) {
    asm volatile(
        "mma.sync.aligned.m16n8k16.row.col.f32.bf16.bf16.f32 "
        "{%0,%1,%2,%3},{%4,%5,%6,%7},{%8,%9},{%0,%1,%2,%3};"
        : "+f"(c[0]), "+f"(c[1]), "+f"(c[2]), "+f"(c[3])
        : "r"(a[0]), "r"(a[1]), "r"(a[2]), "r"(a[3]), "r"(b0), "r"(b1));
}
static __device__ __forceinline__ void cpasync16(unsigned saddr, const void* g) {
    asm volatile("cp.async.cg.shared.global [%0], [%1], 16;"
                 :: "r"(saddr), "l"(g));
}
static __device__ __forceinline__ unsigned pack_bf2(float x, float y) {
    unsigned short a = __bfloat16_as_ushort(__float2bfloat16_rn(x));
    unsigned short b = __bfloat16_as_ushort(__float2bfloat16_rn(y));
    return (unsigned)a | ((unsigned)b << 16);
}
// merge two (min1,min2) 64-bit key pairs (used only in refine over 16 partials)
static __device__ __forceinline__ void merge2(unsigned long long& k1,
                                              unsigned long long& k2,
                                              unsigned long long o1,
                                              unsigned long long o2) {
    unsigned long long n1 = min(k1, o1);
    unsigned long long n2 = min(max(k1, o1), min(k2, o2));
    k1 = n1; k2 = n2;
}

// ---------------- setup kernels ----------------

// z [B][C][HW] -> g_res[r][c] fp32 + g_abf bf16 (depth-0 conversion fused)
__global__ void k_init_transpose(const float* __restrict__ z) {
    __shared__ float T[32][33];
    int b = blockIdx.z, hw0 = blockIdx.y * 32, c0 = blockIdx.x * 32;
    int tx = threadIdx.x & 31, ty0 = threadIdx.x >> 5;
#pragma unroll
    for (int p = 0; p < 4; p++) {
        int cl = ty0 + p * 8;
        T[cl][tx] = z[((size_t)(b * CC + c0 + cl)) * HW + hw0 + tx];
    }
    __syncthreads();
#pragma unroll
    for (int p = 0; p < 4; p++) {
        int hwl = ty0 + p * 8;
        size_t a = (size_t)(b * HW + hw0 + hwl) * CC + c0 + tx;
        float v = T[tx][hwl];
        g_res[a] = v;
        g_abf[a] = __float2bfloat16_rn(v);
    }
}

// codebook norms + bf16 copy + zero counts (once)
__global__ void k_enorm_bf16(const float* __restrict__ cb) {
    int row = blockIdx.x * 8 + (threadIdx.x >> 5);
    int lane = threadIdx.x & 31;
    const float4* p = (const float4*)&cb[(size_t)row * CC + lane * 8];
    float4 v0 = p[0], v1 = p[1];
    uint4 u;
    u.x = pack_bf2(v0.x, v0.y); u.y = pack_bf2(v0.z, v0.w);
    u.z = pack_bf2(v1.x, v1.y); u.w = pack_bf2(v1.z, v1.w);
    *(uint4*)&g_cbbf[(size_t)row * CC + lane * 8] = u;
    float s = v0.x*v0.x + v0.y*v0.y + v0.z*v0.z + v0.w*v0.w
            + v1.x*v1.x + v1.y*v1.y + v1.z*v1.z + v1.w*v1.w;
#pragma unroll
    for (int m = 16; m >= 1; m >>= 1) s += __shfl_xor_sync(0xffffffffu, s, m);
    if (lane == 0) {
        g_enorm[row] = s;
        g_counts[row] = 0;
    }
}

// ---------------- phase 1: bf16 MMA low-precision distances ----------------
// 128 threads, CTA 128x128, warp tile 64x64, cp.async 4-stage pipeline.
// Writes g_tmin[row][group] (8-code group mins) and g_part[row][tile] =
// (min1key, min2key); two-min via parallel float tournament (no serial chain).
__global__ void __launch_bounds__(128) k_lowdist() {
    __shared__ __nv_bfloat16 As[STAGES][CTA_M][40];
    __shared__ __nv_bfloat16 Bs[STAGES][CTA_N][40];
    __shared__ float enS[CTA_N];
    __shared__ ulonglong2 pm[CTA_M][2];

    int tid = threadIdx.x;
    int wid = tid >> 5, l = tid & 31;
    int wm = (wid & 1) * 64, wn = (wid >> 1) * 64;
    int row0 = blockIdx.y * CTA_M, n0 = blockIdx.x * CTA_N;

    enS[tid] = g_enorm[n0 + tid];

    float acc[4][8][4];
#pragma unroll
    for (int i = 0; i < 4; i++)
#pragma unroll
        for (int j = 0; j < 8; j++)
#pragma unroll
            for (int c = 0; c < 4; c++) acc[i][j][c] = 0.0f;

    auto issue = [&](int ch, int st) {
        int kc = ch * 32;
#pragma unroll
        for (int i = 0; i < 4; i++) {
            int idx = tid + i * 128;
            int r = idx >> 2, c16 = idx & 3;
            cpasync16(smem_u32(&As[st][r][c16 * 8]),
                      &g_abf[(size_t)(row0 + r) * CC + kc + c16 * 8]);
        }
#pragma unroll
        for (int i = 0; i < 4; i++) {
            int idx = tid + i * 128;
            int r = idx >> 2, c16 = idx & 3;
            cpasync16(smem_u32(&Bs[st][r][c16 * 8]),
                      &g_cbbf[(size_t)(n0 + r) * CC + kc + c16 * 8]);
        }
        asm volatile("cp.async.commit_group;" ::: "memory");
    };

    issue(0, 0);
    issue(1, 1);
    issue(2, 2);

#pragma unroll
    for (int ch = 0; ch < 8; ch++) {
        if (ch >= 7) {
            asm volatile("cp.async.wait_group 0;" ::: "memory");
        } else if (ch == 6) {
            asm volatile("cp.async.wait_group 1;" ::: "memory");
        } else {
            asm volatile("cp.async.wait_group 2;" ::: "memory");
        }
        __syncthreads();
        if (ch + 3 < 8) issue(ch + 3, (ch + 3) % STAGES);

        int st = ch % STAGES;
#pragma unroll
        for (int kh = 0; kh < 2; kh++) {
            uint32_t a[4][4], bfr[4][4];
#pragma unroll
            for (int i = 0; i < 4; i++) {
                int m = wm + i * 16 + (l & 15);
                unsigned ad = smem_u32(&As[st][m][0]) + ((l >> 4) + kh * 2) * 16;
                ldsm4(a[i], ad);
            }
#pragma unroll
            for (int jj = 0; jj < 4; jj++) {
                int n = wn + jj * 16 + (l & 15);
                unsigned ad = smem_u32(&Bs[st][n][0]) + ((l >> 4) + kh * 2) * 16;
                ldsm4(bfr[jj], ad);
            }
#pragma unroll
            for (int i = 0; i < 4; i++)
#pragma unroll
                for (int j = 0; j < 8; j++)
                    mma16816(acc[i][j], a[i], bfr[j >> 1][j & 1], bfr[j >> 1][(j & 1) + 2]);
        }
    }

    // epilogue: group-of-8 mins (g_tmin) + per-row two-min (float tournament)
#pragma unroll
    for (int i = 0; i < 4; i++) {
#pragma unroll
        for (int h = 0; h < 2; h++) {
            float d0a[8], d1a[8], gv[8], mx[8];
#pragma unroll
            for (int j = 0; j < 8; j++) {
                int nl = wn + j * 8 + (l & 3) * 2;
                d0a[j] = enS[nl]     - 2.0f * acc[i][j][h * 2 + 0];
                d1a[j] = enS[nl + 1] - 2.0f * acc[i][j][h * 2 + 1];
                gv[j] = fminf(d0a[j], d1a[j]);
                mx[j] = fmaxf(d0a[j], d1a[j]);
            }
            // parallel two-min tournament over 8 sorted pairs
            float t1[4], t2[4];
#pragma unroll
            for (int k = 0; k < 4; k++) {
                t1[k] = fminf(gv[2*k], gv[2*k+1]);
                t2[k] = fminf(fmaxf(gv[2*k], gv[2*k+1]), fminf(mx[2*k], mx[2*k+1]));
            }
            float u1[2], u2[2];
#pragma unroll
            for (int k = 0; k < 2; k++) {
                u1[k] = fminf(t1[2*k], t1[2*k+1]);
                u2[k] = fminf(fmaxf(t1[2*k], t1[2*k+1]), fminf(t2[2*k], t2[2*k+1]));
            }
            float m1 = fminf(u1[0], u1[1]);
            float m2 = fminf(fmaxf(u1[0], u1[1]), fminf(u2[0], u2[1]));
            // reduce (m1,m2) over the 4 lanes of this row
#pragma unroll
            for (int mm = 1; mm <= 2; mm <<= 1) {
                float o1 = __shfl_xor_sync(0xffffffffu, m1, mm);
                float o2 = __shfl_xor_sync(0xffffffffu, m2, mm);
                float n1 = fminf(m1, o1);
                m2 = fminf(fmaxf(m1, o1), fminf(m2, o2));
                m1 = n1;
            }
            // argmin code: lowest code matching m1 (desc-j scan, then lane min)
            unsigned cl = 0xFFFFFFFFu;
#pragma unroll
            for (int j = 7; j >= 0; j--) {
                unsigned base = (unsigned)(n0 + wn + j * 8 + (l & 3) * 2);
                if (d1a[j] == m1) cl = base + 1;
                if (d0a[j] == m1) cl = base;
            }
            cl = min(cl, __shfl_xor_sync(0xffffffffu, cl, 1));
            cl = min(cl, __shfl_xor_sync(0xffffffffu, cl, 2));
            // group mins for g_tmin
#pragma unroll
            for (int j = 0; j < 8; j++) {
                gv[j] = fminf(gv[j], __shfl_xor_sync(0xffffffffu, gv[j], 1));
                gv[j] = fminf(gv[j], __shfl_xor_sync(0xffffffffu, gv[j], 2));
            }
            if ((l & 3) == 0) {
                int rloc = wm + i * 16 + h * 8 + (l >> 2);
                float4* dst = (float4*)&g_tmin[(size_t)(row0 + rloc) * (KCODES / 8)
                                               + ((n0 + wn) >> 3)];
                dst[0] = make_float4(gv[0], gv[1], gv[2], gv[3]);
                dst[1] = make_float4(gv[4], gv[5], gv[6], gv[7]);
                unsigned long long k1 =
                    ((unsigned long long)__float_as_uint(4.0f + m1) << 32) | cl;
                unsigned long long k2 =
                    ((unsigned long long)__float_as_uint(4.0f + m2) << 32);
                pm[rloc][wn >> 6] = make_ulonglong2(k1, k2);
            }
        }
    }
    __syncthreads();
    if (tid < CTA_M) {
        ulonglong2 a = pm[tid][0], b = pm[tid][1];
        unsigned long long m1 = min(a.x, b.x);
        unsigned long long m2 = min(max(a.x, b.x), min(a.y, b.y));
        g_part[(size_t)(row0 + tid) * NTILES + blockIdx.x] = make_ulonglong2(m1, m2);
    }
}

// ---------------- phase 2: gap-skip + exact fp32 refine ----------------
#define CLIST 256
__global__ void __launch_bounds__(256) k_refine(const float* __restrict__ cb) {
    __shared__ float zsh[8][256];
    __shared__ int clist[8][CLIST];
    __shared__ int ccnt[8];
    const float MARGIN = 5e-4f;
    const float GAP = 6e-4f;
    int wid = threadIdx.x >> 5, l = threadIdx.x & 31;
    int r = blockIdx.x * 8 + wid;

    // ---- gap decision from g_part (256B per row) ----
    unsigned long long k1 = ~0ull, k2 = ~0ull;
    if (l < NTILES) {
        ulonglong2 p = g_part[(size_t)r * NTILES + l];
        k1 = p.x; k2 = p.y;
    }
#pragma unroll
    for (int m = 1; m <= 8; m <<= 1) {
        unsigned long long o1 = __shfl_xor_sync(0xffffffffu, k1, m);
        unsigned long long o2 = __shfl_xor_sync(0xffffffffu, k2, m);
        merge2(k1, k2, o1, o2);
    }
    k1 = __shfl_sync(0xffffffffu, k1, 0);
    k2 = __shfl_sync(0xffffffffu, k2, 0);
    float m1v = __uint_as_float((unsigned)(k1 >> 32));
    float m2v = __uint_as_float((unsigned)(k2 >> 32));
    if (m2v - m1v > GAP) {
        if (l == 0) g_best[r] = k1;   // gather uses low 32 bits (code index)
        return;
    }

    // ---- undecided: exact refine ----
    const float4* zr = (const float4*)&g_res[(size_t)r * CC];
    float4* zs4 = (float4*)zsh[wid];
    zs4[l] = zr[l];
    zs4[l + 32] = zr[l + 32];
    if (l == 0) ccnt[wid] = 0;
    __syncwarp();

    float zn;
    {
        const float4* p = (const float4*)&zsh[wid][l * 8];
        float4 v0 = p[0], v1 = p[1];
        float s = v0.x*v0.x + v0.y*v0.y + v0.z*v0.z + v0.w*v0.w
                + v1.x*v1.x + v1.y*v1.y + v1.z*v1.z + v1.w*v1.w;
#pragma unroll
        for (int m = 16; m >= 1; m >>= 1) s += __shfl_xor_sync(0xffffffffu, s, m);
        zn = s;
    }

    float v[8];
    const float* tmr = &g_tmin[(size_t)r * (KCODES / 8)];
    float gmin = 3.0e38f;
#pragma unroll
    for (int s = 0; s < 8; s++) {
        v[s] = tmr[s * 32 + l];
        gmin = fminf(gmin, v[s]);
    }
#pragma unroll
    for (int m = 16; m >= 1; m >>= 1)
        gmin = fminf(gmin, __shfl_xor_sync(0xffffffffu, gmin, m));
    float thresh = gmin + MARGIN;

#pragma unroll
    for (int s = 0; s < 8; s++) {
        if (v[s] <= thresh) {
            int g = s * 32 + l;
            int pos = atomicAdd(&ccnt[wid], 8);
            if (pos <= CLIST - 8) {
#pragma unroll
                for (int k = 0; k < 8; k++) clist[wid][pos + k] = g * 8 + k;
            }
        }
    }
    __syncwarp();
    int cnt = ccnt[wid];

    const float4* zc = (const float4*)zsh[wid];
    unsigned long long best = 0xFFFFFFFFFFFFFFFFull;

    if (cnt <= CLIST - 8) {
        for (int base = 0; base < cnt; base += 32) {
            int ci = base + l;
            if (ci < cnt) {
                int code = clist[wid][ci];
                const float4* e4 = (const float4*)&cb[(size_t)code * CC];
                float dot = 0.0f;
#pragma unroll 8
                for (int i = 0; i < 64; i++) {
                    float4 zv = zc[i], ev = e4[i];
                    dot = fmaf(zv.x, ev.x, dot);
                    dot = fmaf(zv.y, ev.y, dot);
                    dot = fmaf(zv.z, ev.z, dot);
                    dot = fmaf(zv.w, ev.w, dot);
                }
                float dist = (zn + g_enorm[code]) - 2.0f * dot;
                unsigned long long key =
                    ((unsigned long long)__float_as_uint(dist) << 32) | (unsigned)code;
                best = min(best, key);
            }
        }
    } else {
        for (int base = 0; base < KCODES; base += 32) {
            int code = base + l;
            const float4* e4 = (const float4*)&cb[(size_t)code * CC];
            float dot = 0.0f;
#pragma unroll 8
            for (int i = 0; i < 64; i++) {
                float4 zv = zc[i], ev = e4[i];
                dot = fmaf(zv.x, ev.x, dot);
                dot = fmaf(zv.y, ev.y, dot);
                dot = fmaf(zv.z, ev.z, dot);
                dot = fmaf(zv.w, ev.w, dot);
            }
            float dist = (zn + g_enorm[code]) - 2.0f * dot;
            unsigned long long key =
                ((unsigned long long)__float_as_uint(dist) << 32) | (unsigned)code;
            best = min(best, key);
        }
    }

#pragma unroll
    for (int m = 16; m >= 1; m >>= 1) {
        unsigned long long o = __shfl_xor_sync(0xffffffffu, best, m);
        best = min(best, o);
    }
    if (l == 0) g_best[r] = best;
}

// ---------------- gather/update/outputs ----------------
__global__ void k_gather_update(const float* __restrict__ cb,
                                float* __restrict__ out_cum,
                                float* __restrict__ out_st,
                                float* __restrict__ out_idx,
                                int d) {
    __shared__ int idx_s[32];
    __shared__ float Tq[32][33];
    __shared__ float Tr[32][33];
    int b = blockIdx.z, hw0 = blockIdx.y * 32, c0 = blockIdx.x * 32;
    int tx = threadIdx.x & 31, ty0 = threadIdx.x >> 5;

    if (threadIdx.x < 32) {
        int r = b * HW + hw0 + threadIdx.x;
        unsigned long long k = g_best[r];
        int idx = (int)(k & 0xFFFFFFFFull);
        idx_s[threadIdx.x] = idx;
        if (c0 == 0) {
            if (out_idx) out_idx[d * NROWS + r] = (float)idx;
            atomicAdd(&g_counts[idx], 1);
        }
    }
    __syncthreads();
#pragma unroll
    for (int p = 0; p < 4; p++) {
        int hwl = ty0 + p * 8;
        int r = b * HW + hw0 + hwl;
        int c = c0 + tx;
        float q = cb[(size_t)idx_s[hwl] * CC + c];
        size_t a = (size_t)r * CC + c;
        float res = g_res[a] - q;
        g_res[a] = res;
        if (d < DEPTH - 1) g_abf[a] = __float2bfloat16_rn(res);
        Tq[tx][hwl] = q;
        Tr[tx][hwl] = res;
    }
    __syncthreads();
#pragma unroll
    for (int p = 0; p < 4; p++) {
        int cl = ty0 + p * 8;
        size_t o = ((size_t)(d * BB + b) * CC + c0 + cl) * HW + hw0 + tx;
        float cum = Tq[cl][tx];
        if (d > 0) {
            size_t oprev = ((size_t)((d - 1) * BB + b) * CC + c0 + cl) * HW + hw0 + tx;
            cum = out_cum[oprev] + cum;
        }
        out_cum[o] = cum;
        if (d == DEPTH - 1 && out_st) {
            out_st[((size_t)b * CC + c0 + cl) * HW + hw0 + tx] = Tr[cl][tx];
        }
    }
}

__global__ void k_perplexity(float* __restrict__ out_perp) {
    __shared__ float red[256];
    float s = 0.0f;
    const float inv = 1.0f / (float)(DEPTH * NROWS);
    for (int k = threadIdx.x; k < KCODES; k += 256) {
        float p = (float)g_counts[k] * inv;
        if (p > 0.0f) s += p * logf(p);
    }
    red[threadIdx.x] = s;
    __syncthreads();
    for (int m = 128; m >= 1; m >>= 1) {
        if (threadIdx.x < m) red[threadIdx.x] += red[threadIdx.x + m];
        __syncthreads();
    }
    if (threadIdx.x == 0) *out_perp = expf(-red[0]);
}

// ---------------- launch ----------------
extern "C" void kernel_launch(void* const* d_in, const int* in_sizes, int n_in,
                              void* d_out, int out_size) {
    const float* z = (const float*)d_in[0];
    const float* cb = (const float*)d_in[1];
    float* out = (float*)d_out;

    const long long SZ_CUM = (long long)DEPTH * BB * CC * HW;
    const long long SZ_ST = (long long)BB * CC * HW;
    const long long SZ_IDX = (long long)DEPTH * NROWS;

    float* out_cum = out;
    float* out_st = (out_size >= SZ_CUM + SZ_ST) ? out + SZ_CUM : nullptr;
    float* out_idx = (out_size >= SZ_CUM + SZ_ST + SZ_IDX) ? out + SZ_CUM + SZ_ST : nullptr;
    float* out_perp = (out_size >= SZ_CUM + SZ_ST + SZ_IDX + 1)
                          ? out + SZ_CUM + SZ_ST + SZ_IDX : nullptr;

    dim3 tgrid(CC / 32, HW / 32, BB);
    k_init_transpose<<<tgrid, 256>>>(z);        // launch 1
    k_enorm_bf16<<<KCODES / 8, 256>>>(cb);      // launch 2 (also zeroes counts)

    for (int d = 0; d < DEPTH; d++) {
        k_lowdist<<<dim3(KCODES / CTA_N, NROWS / CTA_M), 128>>>(); // launch 3 at d=0 -> profiled
        k_refine<<<NROWS / 8, 256>>>(cb);
        k_gather_update<<<tgrid, 256>>>(cb, out_cum, out_st, out_idx, d);
    }
    if (out_perp) k_perplexity<<<1, 256>>>(out_perp);
}

// round 16
// speedup vs baseline: 1.1998x; 1.0581x over previous
#include <cuda_runtime.h>
#include <cuda_bf16.h>
#include <cstdint>

// Problem constants
#define BB 32
#define CC 256
#define HW 1024
#define NROWS 32768
#define KCODES 2048
#define DEPTH 4

// GEMM: CTA 128(M) x 128(N), 128 threads = 4 warps as 2(M) x 2(N), warp 64x64
#define CTA_M 128
#define CTA_N 128
#define STAGES 3
#define NTILES (KCODES / CTA_N)   // 16 partials per row

// ---------------- scratch (device globals; no allocations) ----------------
__device__ float g_res[(size_t)NROWS * CC];        // residual [r][c] fp32
__device__ __nv_bfloat16 g_abf[(size_t)NROWS * CC];// residual bf16 (per depth)
__device__ __nv_bfloat16 g_cbbf[(size_t)KCODES * CC];
__device__ float g_enorm[KCODES];
__device__ float g_tmin[(size_t)NROWS * (KCODES / 8)];  // per 8-code group min
__device__ ulonglong2 g_part[(size_t)NROWS * NTILES];   // per-tile (min1key, min2key)
__device__ unsigned long long g_best[NROWS];
__device__ int g_counts[KCODES];

static __device__ __forceinline__ unsigned smem_u32(const void* p) {
    return (unsigned)__cvta_generic_to_shared(p);
}
static __device__ __forceinline__ void ldsm4(uint32_t* r, unsigned addr) {
    asm volatile("ldmatrix.sync.aligned.m8n8.x4.shared.b16 {%0,%1,%2,%3}, [%4];"
                 : "=r"(r[0]), "=r"(r[1]), "=r"(r[2]), "=r"(r[3]) : "r"(addr));
}
static __device__ __forceinline__ void mma16816(float* c, const uint32_t* a,
                                                uint32_t b0, uint32_t b1) {
    asm volatile(
        "mma.sync.aligned.m16n8k16.row.col.f32.bf16.bf16.f32 "
        "{%0,%1,%2,%3},{%4,%5,%6,%7},{%8,%9},{%0,%1,%2,%3};"
        : "+f"(c[0]), "+f"(c[1]), "+f"(c[2]), "+f"(c[3])
        : "r"(a[0]), "r"(a[1]), "r"(a[2]), "r"(a[3]), "r"(b0), "r"(b1));
}
static __device__ __forceinline__ void cpasync16(unsigned saddr, const void* g) {
    asm volatile("cp.async.cg.shared.global [%0], [%1], 16;"
                 :: "r"(saddr), "l"(g));
}
static __device__ __forceinline__ unsigned pack_bf2(float x, float y) {
    unsigned short a = __bfloat16_as_ushort(__float2bfloat16_rn(x));
    unsigned short b = __bfloat16_as_ushort(__float2bfloat16_rn(y));
    return (unsigned)a | ((unsigned)b << 16);
}
// merge two (min1,min2) 64-bit key pairs (refine partial scan only)
static __device__ __forceinline__ void merge2(unsigned long long& k1,
                                              unsigned long long& k2,
                                              unsigned long long o1,
                                              unsigned long long o2) {
    unsigned long long n1 = min(k1, o1);
    unsigned long long n2 = min(max(k1, o1), min(k2, o2));
    k1 = n1; k2 = n2;
}

// ---------------- setup kernels ----------------

// z [B][C][HW] -> g_res[r][c] fp32 + g_abf bf16 (depth-0 conversion fused)
__global__ void k_init_transpose(const float* __restrict__ z) {
    __shared__ float T[32][33];
    int b = blockIdx.z, hw0 = blockIdx.y * 32, c0 = blockIdx.x * 32;
    int tx = threadIdx.x & 31, ty0 = threadIdx.x >> 5;
#pragma unroll
    for (int p = 0; p < 4; p++) {
        int cl = ty0 + p * 8;
        T[cl][tx] = z[((size_t)(b * CC + c0 + cl)) * HW + hw0 + tx];
    }
    __syncthreads();
#pragma unroll
    for (int p = 0; p < 4; p++) {
        int hwl = ty0 + p * 8;
        size_t a = (size_t)(b * HW + hw0 + hwl) * CC + c0 + tx;
        float v = T[tx][hwl];
        g_res[a] = v;
        g_abf[a] = __float2bfloat16_rn(v);
    }
}

// codebook norms + bf16 copy + zero counts (once)
__global__ void k_enorm_bf16(const float* __restrict__ cb) {
    int row = blockIdx.x * 8 + (threadIdx.x >> 5);
    int lane = threadIdx.x & 31;
    const float4* p = (const float4*)&cb[(size_t)row * CC + lane * 8];
    float4 v0 = p[0], v1 = p[1];
    uint4 u;
    u.x = pack_bf2(v0.x, v0.y); u.y = pack_bf2(v0.z, v0.w);
    u.z = pack_bf2(v1.x, v1.y); u.w = pack_bf2(v1.z, v1.w);
    *(uint4*)&g_cbbf[(size_t)row * CC + lane * 8] = u;
    float s = v0.x*v0.x + v0.y*v0.y + v0.z*v0.z + v0.w*v0.w
            + v1.x*v1.x + v1.y*v1.y + v1.z*v1.z + v1.w*v1.w;
#pragma unroll
    for (int m = 16; m >= 1; m >>= 1) s += __shfl_xor_sync(0xffffffffu, s, m);
    if (lane == 0) {
        g_enorm[row] = s;
        g_counts[row] = 0;
    }
}

// ---------------- phase 1: bf16 MMA low-precision distances ----------------
// 128 threads, CTA 128x128, warp tile 64x64, cp.async 3-stage pipeline,
// 3 CTAs/SM (launch_bounds cap). Writes g_tmin (8-code group mins) and
// g_part (per-tile two-min via parallel float tournament).
__global__ void __launch_bounds__(128, 3) k_lowdist() {
    __shared__ __nv_bfloat16 As[STAGES][CTA_M][40];
    __shared__ __nv_bfloat16 Bs[STAGES][CTA_N][40];
    __shared__ float enS[CTA_N];
    __shared__ ulonglong2 pm[CTA_M][2];

    int tid = threadIdx.x;
    int wid = tid >> 5, l = tid & 31;
    int wm = (wid & 1) * 64, wn = (wid >> 1) * 64;
    int row0 = blockIdx.y * CTA_M, n0 = blockIdx.x * CTA_N;

    enS[tid] = g_enorm[n0 + tid];

    float acc[4][8][4];
#pragma unroll
    for (int i = 0; i < 4; i++)
#pragma unroll
        for (int j = 0; j < 8; j++)
#pragma unroll
            for (int c = 0; c < 4; c++) acc[i][j][c] = 0.0f;

    auto issue = [&](int ch, int st) {
        int kc = ch * 32;
#pragma unroll
        for (int i = 0; i < 4; i++) {
            int idx = tid + i * 128;
            int r = idx >> 2, c16 = idx & 3;
            cpasync16(smem_u32(&As[st][r][c16 * 8]),
                      &g_abf[(size_t)(row0 + r) * CC + kc + c16 * 8]);
        }
#pragma unroll
        for (int i = 0; i < 4; i++) {
            int idx = tid + i * 128;
            int r = idx >> 2, c16 = idx & 3;
            cpasync16(smem_u32(&Bs[st][r][c16 * 8]),
                      &g_cbbf[(size_t)(n0 + r) * CC + kc + c16 * 8]);
        }
        asm volatile("cp.async.commit_group;" ::: "memory");
    };

    issue(0, 0);
    issue(1, 1);

#pragma unroll
    for (int ch = 0; ch < 8; ch++) {
        if (ch == 7) {
            asm volatile("cp.async.wait_group 0;" ::: "memory");
        } else {
            asm volatile("cp.async.wait_group 1;" ::: "memory");
        }
        __syncthreads();
        if (ch + 2 < 8) issue(ch + 2, (ch + 2) % STAGES);

        int st = ch % STAGES;
#pragma unroll
        for (int kh = 0; kh < 2; kh++) {
            uint32_t a[4][4], bfr[4][4];
#pragma unroll
            for (int i = 0; i < 4; i++) {
                int m = wm + i * 16 + (l & 15);
                unsigned ad = smem_u32(&As[st][m][0]) + ((l >> 4) + kh * 2) * 16;
                ldsm4(a[i], ad);
            }
#pragma unroll
            for (int jj = 0; jj < 4; jj++) {
                int n = wn + jj * 16 + (l & 15);
                unsigned ad = smem_u32(&Bs[st][n][0]) + ((l >> 4) + kh * 2) * 16;
                ldsm4(bfr[jj], ad);
            }
#pragma unroll
            for (int i = 0; i < 4; i++)
#pragma unroll
                for (int j = 0; j < 8; j++)
                    mma16816(acc[i][j], a[i], bfr[j >> 1][j & 1], bfr[j >> 1][(j & 1) + 2]);
        }
    }

    // epilogue: group-of-8 mins (g_tmin) + per-row two-min (float tournament)
#pragma unroll
    for (int i = 0; i < 4; i++) {
#pragma unroll
        for (int h = 0; h < 2; h++) {
            float d0a[8], d1a[8], gv[8], mx[8];
#pragma unroll
            for (int j = 0; j < 8; j++) {
                int nl = wn + j * 8 + (l & 3) * 2;
                d0a[j] = enS[nl]     - 2.0f * acc[i][j][h * 2 + 0];
                d1a[j] = enS[nl + 1] - 2.0f * acc[i][j][h * 2 + 1];
                gv[j] = fminf(d0a[j], d1a[j]);
                mx[j] = fmaxf(d0a[j], d1a[j]);
            }
            float t1[4], t2[4];
#pragma unroll
            for (int k = 0; k < 4; k++) {
                t1[k] = fminf(gv[2*k], gv[2*k+1]);
                t2[k] = fminf(fmaxf(gv[2*k], gv[2*k+1]), fminf(mx[2*k], mx[2*k+1]));
            }
            float u1[2], u2[2];
#pragma unroll
            for (int k = 0; k < 2; k++) {
                u1[k] = fminf(t1[2*k], t1[2*k+1]);
                u2[k] = fminf(fmaxf(t1[2*k], t1[2*k+1]), fminf(t2[2*k], t2[2*k+1]));
            }
            float m1 = fminf(u1[0], u1[1]);
            float m2 = fminf(fmaxf(u1[0], u1[1]), fminf(u2[0], u2[1]));
#pragma unroll
            for (int mm = 1; mm <= 2; mm <<= 1) {
                float o1 = __shfl_xor_sync(0xffffffffu, m1, mm);
                float o2 = __shfl_xor_sync(0xffffffffu, m2, mm);
                float n1 = fminf(m1, o1);
                m2 = fminf(fmaxf(m1, o1), fminf(m2, o2));
                m1 = n1;
            }
            unsigned cl = 0xFFFFFFFFu;
#pragma unroll
            for (int j = 7; j >= 0; j--) {
                unsigned base = (unsigned)(n0 + wn + j * 8 + (l & 3) * 2);
                if (d1a[j] == m1) cl = base + 1;
                if (d0a[j] == m1) cl = base;
            }
            cl = min(cl, __shfl_xor_sync(0xffffffffu, cl, 1));
            cl = min(cl, __shfl_xor_sync(0xffffffffu, cl, 2));
#pragma unroll
            for (int j = 0; j < 8; j++) {
                gv[j] = fminf(gv[j], __shfl_xor_sync(0xffffffffu, gv[j], 1));
                gv[j] = fminf(gv[j], __shfl_xor_sync(0xffffffffu, gv[j], 2));
            }
            if ((l & 3) == 0) {
                int rloc = wm + i * 16 + h * 8 + (l >> 2);
                float4* dst = (float4*)&g_tmin[(size_t)(row0 + rloc) * (KCODES / 8)
                                               + ((n0 + wn) >> 3)];
                dst[0] = make_float4(gv[0], gv[1], gv[2], gv[3]);
                dst[1] = make_float4(gv[4], gv[5], gv[6], gv[7]);
                unsigned long long k1 =
                    ((unsigned long long)__float_as_uint(4.0f + m1) << 32) | cl;
                unsigned long long k2 =
                    ((unsigned long long)__float_as_uint(4.0f + m2) << 32);
                pm[rloc][wn >> 6] = make_ulonglong2(k1, k2);
            }
        }
    }
    __syncthreads();
    if (tid < CTA_M) {
        ulonglong2 a = pm[tid][0], b = pm[tid][1];
        unsigned long long m1 = min(a.x, b.x);
        unsigned long long m2 = min(max(a.x, b.x), min(a.y, b.y));
        g_part[(size_t)(row0 + tid) * NTILES + blockIdx.x] = make_ulonglong2(m1, m2);
    }
}

// ---------------- phase 2: gap-skip + exact fp32 refine ----------------
#define CLIST 256
__global__ void __launch_bounds__(256) k_refine(const float* __restrict__ cb) {
    __shared__ float zsh[8][256];
    __shared__ int clist[8][CLIST];
    __shared__ int ccnt[8];
    const float MARGIN = 5e-4f;
    const float GAP = 6e-4f;
    int wid = threadIdx.x >> 5, l = threadIdx.x & 31;
    int r = blockIdx.x * 8 + wid;

    // ---- gap decision from g_part (256B per row) ----
    unsigned long long k1 = ~0ull, k2 = ~0ull;
    if (l < NTILES) {
        ulonglong2 p = g_part[(size_t)r * NTILES + l];
        k1 = p.x; k2 = p.y;
    }
#pragma unroll
    for (int m = 1; m <= 8; m <<= 1) {
        unsigned long long o1 = __shfl_xor_sync(0xffffffffu, k1, m);
        unsigned long long o2 = __shfl_xor_sync(0xffffffffu, k2, m);
        merge2(k1, k2, o1, o2);
    }
    k1 = __shfl_sync(0xffffffffu, k1, 0);
    k2 = __shfl_sync(0xffffffffu, k2, 0);
    float m1v = __uint_as_float((unsigned)(k1 >> 32));
    float m2v = __uint_as_float((unsigned)(k2 >> 32));
    if (m2v - m1v > GAP) {
        if (l == 0) g_best[r] = k1;   // gather uses low 32 bits (code index)
        return;
    }

    // ---- undecided: exact refine ----
    const float4* zr = (const float4*)&g_res[(size_t)r * CC];
    float4* zs4 = (float4*)zsh[wid];
    zs4[l] = zr[l];
    zs4[l + 32] = zr[l + 32];
    if (l == 0) ccnt[wid] = 0;
    __syncwarp();

    float zn;
    {
        const float4* p = (const float4*)&zsh[wid][l * 8];
        float4 v0 = p[0], v1 = p[1];
        float s = v0.x*v0.x + v0.y*v0.y + v0.z*v0.z + v0.w*v0.w
                + v1.x*v1.x + v1.y*v1.y + v1.z*v1.z + v1.w*v1.w;
#pragma unroll
        for (int m = 16; m >= 1; m >>= 1) s += __shfl_xor_sync(0xffffffffu, s, m);
        zn = s;
    }

    float v[8];
    const float* tmr = &g_tmin[(size_t)r * (KCODES / 8)];
    float gmin = 3.0e38f;
#pragma unroll
    for (int s = 0; s < 8; s++) {
        v[s] = tmr[s * 32 + l];
        gmin = fminf(gmin, v[s]);
    }
#pragma unroll
    for (int m = 16; m >= 1; m >>= 1)
        gmin = fminf(gmin, __shfl_xor_sync(0xffffffffu, gmin, m));
    float thresh = gmin + MARGIN;

#pragma unroll
    for (int s = 0; s < 8; s++) {
        if (v[s] <= thresh) {
            int g = s * 32 + l;
            int pos = atomicAdd(&ccnt[wid], 8);
            if (pos <= CLIST - 8) {
#pragma unroll
                for (int k = 0; k < 8; k++) clist[wid][pos + k] = g * 8 + k;
            }
        }
    }
    __syncwarp();
    int cnt = ccnt[wid];

    const float4* zc = (const float4*)zsh[wid];
    unsigned long long best = 0xFFFFFFFFFFFFFFFFull;

    if (cnt <= CLIST - 8) {
        for (int base = 0; base < cnt; base += 32) {
            int ci = base + l;
            if (ci < cnt) {
                int code = clist[wid][ci];
                const float4* e4 = (const float4*)&cb[(size_t)code * CC];
                float dot = 0.0f;
#pragma unroll 8
                for (int i = 0; i < 64; i++) {
                    float4 zv = zc[i], ev = e4[i];
                    dot = fmaf(zv.x, ev.x, dot);
                    dot = fmaf(zv.y, ev.y, dot);
                    dot = fmaf(zv.z, ev.z, dot);
                    dot = fmaf(zv.w, ev.w, dot);
                }
                float dist = (zn + g_enorm[code]) - 2.0f * dot;
                unsigned long long key =
                    ((unsigned long long)__float_as_uint(dist) << 32) | (unsigned)code;
                best = min(best, key);
            }
        }
    } else {
        for (int base = 0; base < KCODES; base += 32) {
            int code = base + l;
            const float4* e4 = (const float4*)&cb[(size_t)code * CC];
            float dot = 0.0f;
#pragma unroll 8
            for (int i = 0; i < 64; i++) {
                float4 zv = zc[i], ev = e4[i];
                dot = fmaf(zv.x, ev.x, dot);
                dot = fmaf(zv.y, ev.y, dot);
                dot = fmaf(zv.z, ev.z, dot);
                dot = fmaf(zv.w, ev.w, dot);
            }
            float dist = (zn + g_enorm[code]) - 2.0f * dot;
            unsigned long long key =
                ((unsigned long long)__float_as_uint(dist) << 32) | (unsigned)code;
            best = min(best, key);
        }
    }

#pragma unroll
    for (int m = 16; m >= 1; m >>= 1) {
        unsigned long long o = __shfl_xor_sync(0xffffffffu, best, m);
        best = min(best, o);
    }
    if (l == 0) g_best[r] = best;
}

// ---------------- gather/update/outputs ----------------
__global__ void k_gather_update(const float* __restrict__ cb,
                                float* __restrict__ out_cum,
                                float* __restrict__ out_st,
                                float* __restrict__ out_idx,
                                int d) {
    __shared__ int idx_s[32];
    __shared__ float Tq[32][33];
    __shared__ float Tr[32][33];
    int b = blockIdx.z, hw0 = blockIdx.y * 32, c0 = blockIdx.x * 32;
    int tx = threadIdx.x & 31, ty0 = threadIdx.x >> 5;

    if (threadIdx.x < 32) {
        int r = b * HW + hw0 + threadIdx.x;
        unsigned long long k = g_best[r];
        int idx = (int)(k & 0xFFFFFFFFull);
        idx_s[threadIdx.x] = idx;
        if (c0 == 0) {
            if (out_idx) out_idx[d * NROWS + r] = (float)idx;
            atomicAdd(&g_counts[idx], 1);
        }
    }
    __syncthreads();
#pragma unroll
    for (int p = 0; p < 4; p++) {
        int hwl = ty0 + p * 8;
        int r = b * HW + hw0 + hwl;
        int c = c0 + tx;
        float q = cb[(size_t)idx_s[hwl] * CC + c];
        size_t a = (size_t)r * CC + c;
        float res = g_res[a] - q;
        if (d < DEPTH - 1) {            // last depth: g_res/g_abf are dead
            g_res[a] = res;
            g_abf[a] = __float2bfloat16_rn(res);
        }
        Tq[tx][hwl] = q;
        Tr[tx][hwl] = res;
    }
    __syncthreads();
#pragma unroll
    for (int p = 0; p < 4; p++) {
        int cl = ty0 + p * 8;
        size_t o = ((size_t)(d * BB + b) * CC + c0 + cl) * HW + hw0 + tx;
        float cum = Tq[cl][tx];
        if (d > 0) {
            size_t oprev = ((size_t)((d - 1) * BB + b) * CC + c0 + cl) * HW + hw0 + tx;
            cum = out_cum[oprev] + cum;
        }
        out_cum[o] = cum;
        if (d == DEPTH - 1 && out_st) {
            out_st[((size_t)b * CC + c0 + cl) * HW + hw0 + tx] = Tr[cl][tx];
        }
    }
}

__global__ void k_perplexity(float* __restrict__ out_perp) {
    __shared__ float red[256];
    float s = 0.0f;
    const float inv = 1.0f / (float)(DEPTH * NROWS);
    for (int k = threadIdx.x; k < KCODES; k += 256) {
        float p = (float)g_counts[k] * inv;
        if (p > 0.0f) s += p * logf(p);
    }
    red[threadIdx.x] = s;
    __syncthreads();
    for (int m = 128; m >= 1; m >>= 1) {
        if (threadIdx.x < m) red[threadIdx.x] += red[threadIdx.x + m];
        __syncthreads();
    }
    if (threadIdx.x == 0) *out_perp = expf(-red[0]);
}

// ---------------- launch ----------------
extern "C" void kernel_launch(void* const* d_in, const int* in_sizes, int n_in,
                              void* d_out, int out_size) {
    const float* z = (const float*)d_in[0];
    const float* cb = (const float*)d_in[1];
    float* out = (float*)d_out;

    const long long SZ_CUM = (long long)DEPTH * BB * CC * HW;
    const long long SZ_ST = (long long)BB * CC * HW;
    const long long SZ_IDX = (long long)DEPTH * NROWS;

    float* out_cum = out;
    float* out_st = (out_size >= SZ_CUM + SZ_ST) ? out + SZ_CUM : nullptr;
    float* out_idx = (out_size >= SZ_CUM + SZ_ST + SZ_IDX) ? out + SZ_CUM + SZ_ST : nullptr;
    float* out_perp = (out_size >= SZ_CUM + SZ_ST + SZ_IDX + 1)
                          ? out + SZ_CUM + SZ_ST + SZ_IDX : nullptr;

    dim3 tgrid(CC / 32, HW / 32, BB);
    k_init_transpose<<<tgrid, 256>>>(z);        // launch 1
    k_enorm_bf16<<<KCODES / 8, 256>>>(cb);      // launch 2 (also zeroes counts)

    for (int d = 0; d < DEPTH; d++) {
        k_lowdist<<<dim3(KCODES / CTA_N, NROWS / CTA_M), 128>>>(); // launch 3 at d=0 -> profiled
        k_refine<<<NROWS / 8, 256>>>(cb);
        k_gather_update<<<tgrid, 256>>>(cb, out_cum, out_st, out_idx, d);
    }
    if (out_perp) k_perplexity<<<1, 256>>>(out_perp);
}